// round 3
// baseline (speedup 1.0000x reference)
#include <cuda_runtime.h>

// RenderLoss: B=262144 batches x MAXC=13 corners.
// R3: warp-autonomous (no __syncthreads), per-warp 3328B smem slice reused for
// input staging then two 16-batch output rounds; launch_bounds(256,7) to get
// 7 blocks/SM (single wave over grid=1024).

constexpr int BATCH = 262144;
constexpr int MAXC  = 13;
constexpr int TPB   = 256;
constexpr int WPB   = TPB / 32;            // 8 warps
constexpr int WBUF  = 32 * MAXC * 2;       // 832 floats = 3328 B per warp
constexpr int IN_F4_W  = WBUF / 4;         // 208 float4 per warp (input)
constexpr int RND_F4_W = 16 * MAXC * 3 / 4;// 156 float4 per 16-batch output round

__global__ __launch_bounds__(TPB, 7) void render_loss_kernel(
    const float* __restrict__ gt,      // [B,13,2] lon,lat
    const int*   __restrict__ nums,    // [B]
    const float* __restrict__ ratio,   // [B]
    float*       __restrict__ out)     // [B,13,3]
{
    __shared__ float smf[WPB * WBUF];  // 26624 B
    const int t = threadIdx.x;
    const int w = t >> 5;
    const int l = t & 31;
    float* buf = smf + w * WBUF;

    const int wbase = blockIdx.x * TPB + w * 32;   // first batch of this warp

    // ---- Phase 1: per-warp coalesced input stage (float4) ----
    const float4* gin = reinterpret_cast<const float4*>(
        gt + (size_t)wbase * (MAXC * 2));
    float4* b4 = reinterpret_cast<float4*>(buf);
    #pragma unroll
    for (int i = 0; i < 7; i++) {
        int idx = l + i * 32;
        if (idx < IN_F4_W) b4[idx] = gin[idx];
    }
    const int   num = nums[wbase + l];
    const float h   = -1.6f * ratio[wbase + l];   // s = h / sin(lat)
    __syncwarp();

    // This lane's (lon,lat) pairs, read from smem per-iteration (no c[] array).
    const float2* cp = reinterpret_cast<const float2*>(buf + l * (MAXC * 2));

    auto corner = [&](float2 ll, float& x, float& z) {
        float sl, cl, so, co;
        __sincosf(ll.y, &sl, &cl);   // lat
        __sincosf(ll.x, &so, &co);   // lon
        float s = __fdividef(h, sl); // |sin(lat)| >= 0.199 -> well-conditioned
        x = cl * so * s;
        z = cl * co * s;
    };

    // ---- Phase 2: compute 13 output normals (kept in registers) ----
    float ox[MAXC], oz[MAXC];

    float x0, z0;
    corner(cp[0], x0, z0);
    float curx = x0, curz = z0;
    float n0x = 0.f, n0z = 0.f;

    #pragma unroll
    for (int j = 0; j < MAXC; j++) {
        float xn = 0.f, zn = 0.f;
        if (j + 1 < MAXC) corner(cp[j + 1], xn, zn);

        const bool last  = (j + 1 == num);       // wrap edge back to corner 0
        const bool valid = (j < num);

        float tx = last ? x0 : xn;
        float tz = last ? z0 : zn;

        float vx = valid ? (tx - curx) : 1.0f;   // invalid -> vec=(1,0,0)
        float vz = valid ? (tz - curz) : 0.0f;

        float rn = rsqrtf(vx * vx + vz * vz);
        float nx = -vz * rn;
        float nz =  vx * rn;

        if (j == 0) { n0x = nx; n0z = nz; }      // num>=4 so j=0 always valid

        float px = 0.f, pz = 0.f;
        if (valid)         { px = nx;  pz = nz;  }
        else if (j == num) { px = n0x; pz = n0z; } // wrap row = normal of edge 0

        ox[j] = px;
        oz[j] = pz;

        curx = xn; curz = zn;
    }

    __syncwarp();   // all lanes done reading input region of the warp buffer

    // ---- Phase 3: two 16-batch output rounds through the same warp buffer ----
    const float4* s4 = reinterpret_cast<const float4*>(buf);
    #pragma unroll
    for (int r = 0; r < 2; r++) {
        if (r) __syncwarp();           // round-0 LDS reads done before overwrite
        if ((l >> 4) == r) {
            float* ob = buf + (l & 15) * (MAXC * 3);  // stride 39 -> conflict-free
            #pragma unroll
            for (int j = 0; j < MAXC; j++) {
                ob[3 * j + 0] = ox[j];
                ob[3 * j + 1] = 0.0f;
                ob[3 * j + 2] = oz[j];
            }
        }
        __syncwarp();
        float4* gout = reinterpret_cast<float4*>(
            out + (size_t)(wbase + r * 16) * (MAXC * 3));
        #pragma unroll
        for (int i = 0; i < 5; i++) {
            int idx = l + i * 32;
            if (idx < RND_F4_W) gout[idx] = s4[idx];
        }
    }
}

extern "C" void kernel_launch(void* const* d_in, const int* in_sizes, int n_in,
                              void* d_out, int out_size)
{
    const float* gt    = (const float*)d_in[0];  // GT_up [B,13,2] f32
    const int*   nums  = (const int*)  d_in[1];  // corner_nums [B] i32
    const float* ratio = (const float*)d_in[2];  // up_down_ratio [B] f32
    float*       out   = (float*)d_out;          // [B,13,3] f32

    render_loss_kernel<<<BATCH / TPB, TPB>>>(gt, nums, ratio, out);
}

// round 4
// speedup vs baseline: 1.5038x; 1.5038x over previous
#include <cuda_runtime.h>

// RenderLoss: B=262144 batches x MAXC=13 corners.
// R4: warp-autonomous (only __syncwarp), per-warp 4992B smem slice
// (input staging reuses low 3328B, then single 32-batch output round),
// compute fully register-resident (R2-style). 5 blocks/SM (regfile limit).

constexpr int BATCH = 262144;
constexpr int MAXC  = 13;
constexpr int TPB   = 256;
constexpr int WPB   = TPB / 32;             // 8 warps
constexpr int WBUF  = 32 * MAXC * 3;        // 1248 floats = 4992 B per warp
constexpr int IN_F4_W  = 32 * MAXC * 2 / 4; // 208 float4 per warp (input)
constexpr int OUT_F4_W = WBUF / 4;          // 312 float4 per warp (output)

__global__ __launch_bounds__(TPB, 5) void render_loss_kernel(
    const float* __restrict__ gt,      // [B,13,2] lon,lat
    const int*   __restrict__ nums,    // [B]
    const float* __restrict__ ratio,   // [B]
    float*       __restrict__ out)     // [B,13,3]
{
    __shared__ float smf[WPB * WBUF];  // 39936 B
    const int t = threadIdx.x;
    const int w = t >> 5;
    const int l = t & 31;
    float* buf = smf + w * WBUF;

    const int wbase = blockIdx.x * TPB + w * 32;   // first batch of this warp

    // ---- Phase 1: per-warp coalesced input stage (float4) ----
    const float4* gin = reinterpret_cast<const float4*>(
        gt + (size_t)wbase * (MAXC * 2));
    float4* b4 = reinterpret_cast<float4*>(buf);
    #pragma unroll
    for (int i = 0; i < 7; i++) {
        int idx = l + i * 32;
        if (idx < IN_F4_W) b4[idx] = gin[idx];
    }
    const int   num = nums[wbase + l];
    const float h   = -1.6f * ratio[wbase + l];   // s = h / sin(lat)
    __syncwarp();

    // This lane's 13 (lon,lat) pairs -> registers.
    float2 c[MAXC];
    const float2* cp = reinterpret_cast<const float2*>(buf + l * (MAXC * 2));
    #pragma unroll
    for (int j = 0; j < MAXC; j++) c[j] = cp[j];
    __syncwarp();   // input region about to be overwritten by output staging

    // ---- Phase 2: compute all 13 output normals in registers ----
    auto corner = [&](float2 ll, float& x, float& z) {
        float sl, cl, so, co;
        __sincosf(ll.y, &sl, &cl);   // lat
        __sincosf(ll.x, &so, &co);   // lon
        float s = __fdividef(h, sl); // |sin(lat)| >= 0.199 -> well-conditioned
        x = cl * so * s;
        z = cl * co * s;
    };

    float ox[MAXC], oz[MAXC];

    float x0, z0;
    corner(c[0], x0, z0);
    float curx = x0, curz = z0;
    float n0x = 0.f, n0z = 0.f;

    #pragma unroll
    for (int j = 0; j < MAXC; j++) {
        float xn = 0.f, zn = 0.f;
        if (j + 1 < MAXC) corner(c[j + 1], xn, zn);

        const bool last  = (j + 1 == num);       // wrap edge back to corner 0
        const bool valid = (j < num);

        float tx = last ? x0 : xn;
        float tz = last ? z0 : zn;

        float vx = valid ? (tx - curx) : 1.0f;   // invalid -> vec=(1,0,0)
        float vz = valid ? (tz - curz) : 0.0f;

        float rn = rsqrtf(vx * vx + vz * vz);
        float nx = -vz * rn;
        float nz =  vx * rn;

        if (j == 0) { n0x = nx; n0z = nz; }      // num>=4 so j=0 always valid

        float px = 0.f, pz = 0.f;
        if (valid)         { px = nx;  pz = nz;  }
        else if (j == num) { px = n0x; pz = n0z; } // wrap row = normal of edge 0

        ox[j] = px;
        oz[j] = pz;

        curx = xn; curz = zn;
    }

    // ---- Phase 3: stage all 32 batches' output, single coalesced store ----
    {
        float* ob = buf + l * (MAXC * 3);   // stride 39 (odd) -> conflict-free
        #pragma unroll
        for (int j = 0; j < MAXC; j++) {
            ob[3 * j + 0] = ox[j];
            ob[3 * j + 1] = 0.0f;
            ob[3 * j + 2] = oz[j];
        }
    }
    __syncwarp();

    const float4* s4 = reinterpret_cast<const float4*>(buf);
    float4* gout = reinterpret_cast<float4*>(
        out + (size_t)wbase * (MAXC * 3));
    #pragma unroll
    for (int i = 0; i < 10; i++) {
        int idx = l + i * 32;
        if (idx < OUT_F4_W) gout[idx] = s4[idx];
    }
}

extern "C" void kernel_launch(void* const* d_in, const int* in_sizes, int n_in,
                              void* d_out, int out_size)
{
    const float* gt    = (const float*)d_in[0];  // GT_up [B,13,2] f32
    const int*   nums  = (const int*)  d_in[1];  // corner_nums [B] i32
    const float* ratio = (const float*)d_in[2];  // up_down_ratio [B] f32
    float*       out   = (float*)d_out;          // [B,13,3] f32

    render_loss_kernel<<<BATCH / TPB, TPB>>>(gt, nums, ratio, out);
}